// round 2
// baseline (speedup 1.0000x reference)
#include <cuda_runtime.h>

// Problem constants
#define B_   2
#define S_   2048
#define H_   16
#define DK_  64
#define DM_  1024
#define SCALE_ 0.125f   // 1/sqrt(64)

// Scratch for un-projected attention output: [B, S, DM] fp32 = 16 MB
__device__ float g_attn[(size_t)B_ * S_ * DM_];

// ---------------------------------------------------------------------------
// Flash-attention (fp32, online softmax).
// Grid: (S/64, H, B). Block: 256 threads = 16x16, each owns a 4x4 micro-tile.
// Dynamic smem: Qs[64][65] + Ks[64][65] + Ps[64][65] + Vs[64][64]
// ---------------------------------------------------------------------------
__global__ __launch_bounds__(256) void attn_kernel(const float* __restrict__ q,
                                                   const float* __restrict__ k,
                                                   const float* __restrict__ v) {
    extern __shared__ float sm[];
    float* Qs = sm;                       // 64*65
    float* Ks = Qs + 64 * 65;             // 64*65
    float* Ps = Ks + 64 * 65;             // 64*65
    float* Vs = Ps + 64 * 65;             // 64*64 (16B-aligned: 3*65*64*4 = 49920 bytes)

    const int t  = threadIdx.x;
    const int tx = t & 15;                // 0..15 -> 4 output columns (d / n)
    const int ty = t >> 4;                // 0..15 -> 4 query rows

    const int b  = blockIdx.z;
    const int h  = blockIdx.y;
    const int q0 = blockIdx.x * 64;

    const size_t base = (size_t)b * S_ * DM_ + (size_t)h * DK_;

    // Load Q tile (scale folded in)
    for (int i = t; i < 64 * 64; i += 256) {
        int r = i >> 6, d = i & 63;
        Qs[r * 65 + d] = q[base + (size_t)(q0 + r) * DM_ + d] * SCALE_;
    }

    float acc[4][4] = {};
    float m[4], l[4];
#pragma unroll
    for (int i = 0; i < 4; ++i) { m[i] = -1e30f; l[i] = 0.0f; }

    for (int kt = 0; kt < S_ / 64; ++kt) {
        __syncthreads();   // protect Ks/Vs vs previous AV reads; first iter: Qs visible after next sync
        const int k0 = kt * 64;
        for (int i = t; i < 64 * 64; i += 256) {
            int r = i >> 6, d = i & 63;
            Ks[r * 65 + d] = k[base + (size_t)(k0 + r) * DM_ + d];
        }
        for (int i = t; i < 64 * 16; i += 256) {
            int r = i >> 4, c4 = i & 15;
            *(float4*)&Vs[r * 64 + c4 * 4] =
                *(const float4*)&v[base + (size_t)(k0 + r) * DM_ + c4 * 4];
        }
        __syncthreads();

        // S = Q K^T  (4x4 per thread)
        float s[4][4] = {};
#pragma unroll 8
        for (int dd = 0; dd < 64; ++dd) {
            float a0 = Qs[(4 * ty + 0) * 65 + dd];
            float a1 = Qs[(4 * ty + 1) * 65 + dd];
            float a2 = Qs[(4 * ty + 2) * 65 + dd];
            float a3 = Qs[(4 * ty + 3) * 65 + dd];
            float b0 = Ks[(4 * tx + 0) * 65 + dd];
            float b1 = Ks[(4 * tx + 1) * 65 + dd];
            float b2 = Ks[(4 * tx + 2) * 65 + dd];
            float b3 = Ks[(4 * tx + 3) * 65 + dd];
            s[0][0] += a0 * b0; s[0][1] += a0 * b1; s[0][2] += a0 * b2; s[0][3] += a0 * b3;
            s[1][0] += a1 * b0; s[1][1] += a1 * b1; s[1][2] += a1 * b2; s[1][3] += a1 * b3;
            s[2][0] += a2 * b0; s[2][1] += a2 * b1; s[2][2] += a2 * b2; s[2][3] += a2 * b3;
            s[3][0] += a3 * b0; s[3][1] += a3 * b1; s[3][2] += a3 * b2; s[3][3] += a3 * b3;
        }

        // Online softmax per query row (row shared by 16 tx lanes within a
        // 16-lane shfl segment: warp = 2 ty values x 16 tx lanes)
#pragma unroll
        for (int i = 0; i < 4; ++i) {
            float tmax = fmaxf(fmaxf(s[i][0], s[i][1]), fmaxf(s[i][2], s[i][3]));
#pragma unroll
            for (int o = 8; o > 0; o >>= 1)
                tmax = fmaxf(tmax, __shfl_xor_sync(0xffffffffu, tmax, o, 16));
            float mnew = fmaxf(m[i], tmax);
            float corr = __expf(m[i] - mnew);
            float psum = 0.0f;
#pragma unroll
            for (int j = 0; j < 4; ++j) {
                float p = __expf(s[i][j] - mnew);
                psum += p;
                Ps[(4 * ty + i) * 65 + 4 * tx + j] = p;
            }
#pragma unroll
            for (int o = 8; o > 0; o >>= 1)
                psum += __shfl_xor_sync(0xffffffffu, psum, o, 16);
            l[i] = l[i] * corr + psum;
            m[i] = mnew;
#pragma unroll
            for (int j = 0; j < 4; ++j) acc[i][j] *= corr;
        }
        __syncthreads();

        // O += P V  (same 4x4 micro-tile; thread owns d-cols 4*tx..4*tx+3)
#pragma unroll 4
        for (int j = 0; j < 64; ++j) {
            float4 vv = *(float4*)&Vs[j * 64 + 4 * tx];
#pragma unroll
            for (int i = 0; i < 4; ++i) {
                float pv = Ps[(4 * ty + i) * 65 + j];
                acc[i][0] += pv * vv.x;
                acc[i][1] += pv * vv.y;
                acc[i][2] += pv * vv.z;
                acc[i][3] += pv * vv.w;
            }
        }
    }

    // Normalize + store to scratch
#pragma unroll
    for (int i = 0; i < 4; ++i) {
        float inv = 1.0f / l[i];
        int row = q0 + 4 * ty + i;
        float4 o4 = make_float4(acc[i][0] * inv, acc[i][1] * inv,
                                acc[i][2] * inv, acc[i][3] * inv);
        *(float4*)&g_attn[base + (size_t)row * DM_ + 4 * tx] = o4;
    }
}

// ---------------------------------------------------------------------------
// Output projection: C[M, N] = A[M, K] @ W[N, K]^T + bias[N]
// M = B*S = 4096, N = K = 1024.  Grid: (N/64, M/64). Block 256, 4x4 micro-tile.
// ---------------------------------------------------------------------------
__global__ __launch_bounds__(256) void proj_kernel(const float* __restrict__ W,
                                                   const float* __restrict__ bias,
                                                   float* __restrict__ C) {
    __shared__ float As[64 * 33];
    __shared__ float Ws[64 * 33];

    const int t  = threadIdx.x;
    const int tx = t & 15;
    const int ty = t >> 4;
    const int j0 = blockIdx.x * 64;
    const int i0 = blockIdx.y * 64;

    const float* A = g_attn;
    float acc[4][4] = {};

    for (int k0 = 0; k0 < DM_; k0 += 32) {
        __syncthreads();
        for (int i = t; i < 64 * 32; i += 256) {
            int r = i >> 5, c = i & 31;
            As[r * 33 + c] = A[(size_t)(i0 + r) * DM_ + k0 + c];
            Ws[r * 33 + c] = W[(size_t)(j0 + r) * DM_ + k0 + c];
        }
        __syncthreads();
#pragma unroll 8
        for (int kk = 0; kk < 32; ++kk) {
            float a0 = As[(4 * ty + 0) * 33 + kk];
            float a1 = As[(4 * ty + 1) * 33 + kk];
            float a2 = As[(4 * ty + 2) * 33 + kk];
            float a3 = As[(4 * ty + 3) * 33 + kk];
            float w0 = Ws[(4 * tx + 0) * 33 + kk];
            float w1 = Ws[(4 * tx + 1) * 33 + kk];
            float w2 = Ws[(4 * tx + 2) * 33 + kk];
            float w3 = Ws[(4 * tx + 3) * 33 + kk];
            acc[0][0] += a0 * w0; acc[0][1] += a0 * w1; acc[0][2] += a0 * w2; acc[0][3] += a0 * w3;
            acc[1][0] += a1 * w0; acc[1][1] += a1 * w1; acc[1][2] += a1 * w2; acc[1][3] += a1 * w3;
            acc[2][0] += a2 * w0; acc[2][1] += a2 * w1; acc[2][2] += a2 * w2; acc[2][3] += a2 * w3;
            acc[3][0] += a3 * w0; acc[3][1] += a3 * w1; acc[3][2] += a3 * w2; acc[3][3] += a3 * w3;
        }
    }

#pragma unroll
    for (int i = 0; i < 4; ++i) {
        int row = i0 + 4 * ty + i;
#pragma unroll
        for (int j = 0; j < 4; ++j) {
            int col = j0 + 4 * tx + j;
            C[(size_t)row * DM_ + col] = acc[i][j] + bias[col];
        }
    }
}

// ---------------------------------------------------------------------------
// Launch
// ---------------------------------------------------------------------------
extern "C" void kernel_launch(void* const* d_in, const int* in_sizes, int n_in,
                              void* d_out, int out_size) {
    const float* q    = (const float*)d_in[0];
    const float* k    = (const float*)d_in[1];
    const float* v    = (const float*)d_in[2];
    const float* W    = (const float*)d_in[3];
    const float* bias = (const float*)d_in[4];
    float* out = (float*)d_out;

    const size_t attn_smem = (3 * 65 * 64 + 64 * 64) * sizeof(float);  // ~64.8 KB
    cudaFuncSetAttribute(attn_kernel, cudaFuncAttributeMaxDynamicSharedMemorySize,
                         (int)attn_smem);

    attn_kernel<<<dim3(S_ / 64, H_, B_), 256, attn_smem>>>(q, k, v);
    proj_kernel<<<dim3(DM_ / 64, (B_ * S_) / 64), 256>>>(W, bias, out);
}

// round 4
// speedup vs baseline: 3.6944x; 3.6944x over previous
#include <cuda_runtime.h>
#include <cuda_bf16.h>
#include <stdint.h>

#define B_   2
#define S_   2048
#define H_   16
#define DK_  64
#define DM_  1024
#define SCALE_ 0.125f

// Scratch for un-projected attention output: [B, S, DM] fp32 = 16 MB
__device__ float g_attn[(size_t)B_ * S_ * DM_];

// ---------------------------------------------------------------------------
// Helpers (baseline PTX only: ldmatrix + mma.sync — no arch-suffix features)
// ---------------------------------------------------------------------------
__device__ __forceinline__ uint32_t smem_u32(const void* p) {
    uint32_t a;
    asm("{ .reg .u64 t; cvta.to.shared.u64 t, %1; cvt.u32.u64 %0, t; }"
        : "=r"(a) : "l"(p));
    return a;
}
#define SW128F(o) ((o) ^ (((o) >> 3) & 0x70))

__device__ __forceinline__ void ldsm4(uint32_t r[4], uint32_t addr) {
    asm volatile("ldmatrix.sync.aligned.m8n8.x4.shared.b16 {%0,%1,%2,%3}, [%4];"
                 : "=r"(r[0]), "=r"(r[1]), "=r"(r[2]), "=r"(r[3]) : "r"(addr));
}
__device__ __forceinline__ void ldsm4t(uint32_t r[4], uint32_t addr) {
    asm volatile("ldmatrix.sync.aligned.m8n8.x4.trans.shared.b16 {%0,%1,%2,%3}, [%4];"
                 : "=r"(r[0]), "=r"(r[1]), "=r"(r[2]), "=r"(r[3]) : "r"(addr));
}
__device__ __forceinline__ void mma16816(float c[4], const uint32_t a[4],
                                         uint32_t b0, uint32_t b1) {
    asm volatile("mma.sync.aligned.m16n8k16.row.col.f32.bf16.bf16.f32 "
                 "{%0,%1,%2,%3}, {%4,%5,%6,%7}, {%8,%9}, {%0,%1,%2,%3};"
                 : "+f"(c[0]), "+f"(c[1]), "+f"(c[2]), "+f"(c[3])
                 : "r"(a[0]), "r"(a[1]), "r"(a[2]), "r"(a[3]), "r"(b0), "r"(b1));
}
__device__ __forceinline__ uint32_t packbf2(float a, float b) {
    __nv_bfloat162 h = __floats2bfloat162_rn(a, b);
    return *(uint32_t*)&h;
}

// Tile loader: 128 rows x 64 fp32 -> bf16 hi/lo into SW128-swizzled smem
// (rows of 128 bytes). 256 threads.
__device__ __forceinline__ void load_hilo(char* smem, uint32_t offh, uint32_t offl,
                                          const float* __restrict__ src,
                                          int ld, float scale, int t) {
    for (int i = t; i < 128 * 16; i += 256) {
        int r = i >> 4, c4 = i & 15;
        float4 x = *(const float4*)(src + (size_t)r * ld + c4 * 4);
        x.x *= scale; x.y *= scale; x.z *= scale; x.w *= scale;
        __nv_bfloat16 ha = __float2bfloat16(x.x), hb = __float2bfloat16(x.y);
        __nv_bfloat16 hc = __float2bfloat16(x.z), hd = __float2bfloat16(x.w);
        uint32_t H0, H1, L0, L1;
        { __nv_bfloat162 v = __halves2bfloat162(ha, hb); H0 = *(uint32_t*)&v; }
        { __nv_bfloat162 v = __halves2bfloat162(hc, hd); H1 = *(uint32_t*)&v; }
        L0 = packbf2(x.x - __bfloat162float(ha), x.y - __bfloat162float(hb));
        L1 = packbf2(x.z - __bfloat162float(hc), x.w - __bfloat162float(hd));
        uint32_t swo = SW128F((uint32_t)(r * 128 + c4 * 8));
        *(uint32_t*)(smem + offh + swo)     = H0;
        *(uint32_t*)(smem + offh + swo + 4) = H1;
        *(uint32_t*)(smem + offl + swo)     = L0;
        *(uint32_t*)(smem + offl + swo + 4) = L1;
    }
}

// ---------------------------------------------------------------------------
// Attention: CTA = (b, h, 128-query tile), 256 threads / 8 warps.
// Warp w owns query rows [w*16, w*16+16). Online softmax, P stays in registers.
// ---------------------------------------------------------------------------
#define SQH 0
#define SQL 16384
#define SKH 32768
#define SKL 49152
#define SVH 65536
#define SVL 81920
#define SM_ATT (6 * 16384)   // 96 KB

__global__ __launch_bounds__(256) void attn_mma(const float* __restrict__ q,
                                                const float* __restrict__ k,
                                                const float* __restrict__ v) {
    extern __shared__ char smem[];
    const uint32_t sb = smem_u32(smem);
    const int t = threadIdx.x;
    const int w = t >> 5, l = t & 31;
    const int gid = l >> 2, tid = l & 3;
    const int mq = w * 16;

    const int b = blockIdx.z, h = blockIdx.y, q0 = blockIdx.x * 128;
    const size_t base = (size_t)b * S_ * DM_ + (size_t)h * DK_;

    // Q tile (scale folded in; x0.125 is exact so hi/lo split unaffected)
    load_hilo(smem, SQH, SQL, q + base + (size_t)q0 * DM_, DM_, SCALE_, t);

    float accO[8][4];
#pragma unroll
    for (int i = 0; i < 8; ++i)
#pragma unroll
        for (int j = 0; j < 4; ++j) accO[i][j] = 0.0f;
    float m0 = -1e30f, m1 = -1e30f, l0 = 0.0f, l1 = 0.0f;

    // per-lane ldmatrix address components
    const uint32_t lrow = (uint32_t)(l & 15);
    const uint32_t lhalf = (uint32_t)(l & 16);   // 0 or 16 bytes (k half)

    for (int kt = 0; kt < 16; ++kt) {
        __syncthreads();   // previous iter's ldmatrix reads complete (covers Q stores on kt=0)
        const int k0 = kt * 128;
        load_hilo(smem, SKH, SKL, k + base + (size_t)k0 * DM_, DM_, 1.0f, t);
        load_hilo(smem, SVH, SVL, v + base + (size_t)k0 * DM_, DM_, 1.0f, t);
        __syncthreads();

        // ---- S = Q K^T  (M16 x N128 per warp), 3-pass hi/lo ----
        float accS[16][4];
#pragma unroll
        for (int i = 0; i < 16; ++i)
#pragma unroll
            for (int j = 0; j < 4; ++j) accS[i][j] = 0.0f;

#pragma unroll
        for (int ks = 0; ks < 4; ++ks) {
            uint32_t ah[4], al[4];
            uint32_t swa = SW128F((uint32_t)((mq + lrow) * 128) + ks * 32 + lhalf);
            ldsm4(ah, sb + SQH + swa);
            ldsm4(al, sb + SQL + swa);
#pragma unroll
            for (int np = 0; np < 8; ++np) {
                uint32_t bh[4], bl[4];
                uint32_t swb = SW128F((uint32_t)((np * 16 + lrow) * 128) + ks * 32 + lhalf);
                ldsm4(bh, sb + SKH + swb);
                ldsm4(bl, sb + SKL + swb);
                // hi*hi
                mma16816(accS[2 * np],     ah, bh[0], bh[2]);
                mma16816(accS[2 * np + 1], ah, bh[1], bh[3]);
                // hi*lo
                mma16816(accS[2 * np],     ah, bl[0], bl[2]);
                mma16816(accS[2 * np + 1], ah, bl[1], bl[3]);
                // lo*hi
                mma16816(accS[2 * np],     al, bh[0], bh[2]);
                mma16816(accS[2 * np + 1], al, bh[1], bh[3]);
            }
        }

        // ---- online softmax: thread owns rows gid (c0,c1) and gid+8 (c2,c3) ----
        float mx0 = -1e30f, mx1 = -1e30f;
#pragma unroll
        for (int nt = 0; nt < 16; ++nt) {
            mx0 = fmaxf(mx0, fmaxf(accS[nt][0], accS[nt][1]));
            mx1 = fmaxf(mx1, fmaxf(accS[nt][2], accS[nt][3]));
        }
        mx0 = fmaxf(mx0, __shfl_xor_sync(0xffffffffu, mx0, 1));
        mx0 = fmaxf(mx0, __shfl_xor_sync(0xffffffffu, mx0, 2));
        mx1 = fmaxf(mx1, __shfl_xor_sync(0xffffffffu, mx1, 1));
        mx1 = fmaxf(mx1, __shfl_xor_sync(0xffffffffu, mx1, 2));
        float mn0 = fmaxf(m0, mx0), mn1 = fmaxf(m1, mx1);
        float c0 = __expf(m0 - mn0), c1 = __expf(m1 - mn1);
        m0 = mn0; m1 = mn1;

        float s0 = 0.0f, s1 = 0.0f;
#pragma unroll
        for (int nt = 0; nt < 16; ++nt) {
            float p0 = __expf(accS[nt][0] - mn0);
            float p1 = __expf(accS[nt][1] - mn0);
            float p2 = __expf(accS[nt][2] - mn1);
            float p3 = __expf(accS[nt][3] - mn1);
            s0 += p0 + p1; s1 += p2 + p3;
            accS[nt][0] = p0; accS[nt][1] = p1; accS[nt][2] = p2; accS[nt][3] = p3;
        }
        s0 += __shfl_xor_sync(0xffffffffu, s0, 1);
        s0 += __shfl_xor_sync(0xffffffffu, s0, 2);
        s1 += __shfl_xor_sync(0xffffffffu, s1, 1);
        s1 += __shfl_xor_sync(0xffffffffu, s1, 2);
        l0 = l0 * c0 + s0;
        l1 = l1 * c1 + s1;
#pragma unroll
        for (int nt = 0; nt < 8; ++nt) {
            accO[nt][0] *= c0; accO[nt][1] *= c0;
            accO[nt][2] *= c1; accO[nt][3] *= c1;
        }

        // ---- O += P V : P(C-frag) == A-frag layout; V via ldmatrix.trans ----
#pragma unroll
        for (int kk = 0; kk < 8; ++kk) {
            uint32_t ph[4], pl[4];
#pragma unroll
            for (int half = 0; half < 2; ++half) {
                float pA = accS[2 * kk + half][0], pB = accS[2 * kk + half][1];
                float pC = accS[2 * kk + half][2], pD = accS[2 * kk + half][3];
                __nv_bfloat16 hA = __float2bfloat16(pA), hB = __float2bfloat16(pB);
                __nv_bfloat16 hC = __float2bfloat16(pC), hD = __float2bfloat16(pD);
                { __nv_bfloat162 vv = __halves2bfloat162(hA, hB); ph[2 * half] = *(uint32_t*)&vv; }
                { __nv_bfloat162 vv = __halves2bfloat162(hC, hD); ph[2 * half + 1] = *(uint32_t*)&vv; }
                pl[2 * half]     = packbf2(pA - __bfloat162float(hA), pB - __bfloat162float(hB));
                pl[2 * half + 1] = packbf2(pC - __bfloat162float(hC), pD - __bfloat162float(hD));
            }
#pragma unroll
            for (int np = 0; np < 4; ++np) {
                uint32_t vh[4], vl[4];
                uint32_t swv = SW128F((uint32_t)((kk * 16 + lrow) * 128) + np * 32 + lhalf);
                ldsm4t(vh, sb + SVH + swv);
                ldsm4t(vl, sb + SVL + swv);
                mma16816(accO[2 * np],     ph, vh[0], vh[1]);
                mma16816(accO[2 * np + 1], ph, vh[2], vh[3]);
                mma16816(accO[2 * np],     ph, vl[0], vl[1]);
                mma16816(accO[2 * np + 1], ph, vl[2], vl[3]);
                mma16816(accO[2 * np],     pl, vh[0], vh[1]);
                mma16816(accO[2 * np + 1], pl, vh[2], vh[3]);
            }
        }
    }

    // ---- epilogue ----
    float inv0 = 1.0f / l0, inv1 = 1.0f / l1;
    const int r0 = q0 + mq + gid, r1 = r0 + 8;
#pragma unroll
    for (int nt = 0; nt < 8; ++nt) {
        int col = nt * 8 + 2 * tid;
        float2 o0 = make_float2(accO[nt][0] * inv0, accO[nt][1] * inv0);
        float2 o1 = make_float2(accO[nt][2] * inv1, accO[nt][3] * inv1);
        *(float2*)(g_attn + base + (size_t)r0 * DM_ + col) = o0;
        *(float2*)(g_attn + base + (size_t)r1 * DM_ + col) = o1;
    }
}

// ---------------------------------------------------------------------------
// Projection: C[4096,1024] = A @ W^T + bias. 128x128 tile/CTA, 8 warps.
// ---------------------------------------------------------------------------
#define PAH 0
#define PAL 16384
#define PWH 32768
#define PWL 49152
#define SM_PROJ (4 * 16384)   // 64 KB

__global__ __launch_bounds__(256) void proj_mma(const float* __restrict__ Wm,
                                                const float* __restrict__ bias,
                                                float* __restrict__ C) {
    extern __shared__ char smem[];
    const uint32_t sb = smem_u32(smem);
    const int t = threadIdx.x;
    const int w = t >> 5, l = t & 31;
    const int gid = l >> 2, tid = l & 3;
    const int mq = w * 16;
    const int j0 = blockIdx.x * 128, i0 = blockIdx.y * 128;

    float acc[16][4];
#pragma unroll
    for (int i = 0; i < 16; ++i)
#pragma unroll
        for (int j = 0; j < 4; ++j) acc[i][j] = 0.0f;

    const uint32_t lrow = (uint32_t)(l & 15);
    const uint32_t lhalf = (uint32_t)(l & 16);

    for (int kc = 0; kc < 16; ++kc) {
        __syncthreads();
        load_hilo(smem, PAH, PAL, g_attn + (size_t)i0 * DM_ + kc * 64, DM_, 1.0f, t);
        load_hilo(smem, PWH, PWL, Wm + (size_t)j0 * DM_ + kc * 64, DM_, 1.0f, t);
        __syncthreads();

#pragma unroll
        for (int ks = 0; ks < 4; ++ks) {
            uint32_t ah[4], al[4];
            uint32_t swa = SW128F((uint32_t)((mq + lrow) * 128) + ks * 32 + lhalf);
            ldsm4(ah, sb + PAH + swa);
            ldsm4(al, sb + PAL + swa);
#pragma unroll
            for (int np = 0; np < 8; ++np) {
                uint32_t bh[4], bl[4];
                uint32_t swb = SW128F((uint32_t)((np * 16 + lrow) * 128) + ks * 32 + lhalf);
                ldsm4(bh, sb + PWH + swb);
                ldsm4(bl, sb + PWL + swb);
                mma16816(acc[2 * np],     ah, bh[0], bh[2]);
                mma16816(acc[2 * np + 1], ah, bh[1], bh[3]);
                mma16816(acc[2 * np],     ah, bl[0], bl[2]);
                mma16816(acc[2 * np + 1], ah, bl[1], bl[3]);
                mma16816(acc[2 * np],     al, bh[0], bh[2]);
                mma16816(acc[2 * np + 1], al, bh[1], bh[3]);
            }
        }
    }

    const int r0 = i0 + mq + gid, r1 = r0 + 8;
#pragma unroll
    for (int nt = 0; nt < 16; ++nt) {
        int col = j0 + nt * 8 + 2 * tid;
        float b0 = bias[col], b1 = bias[col + 1];
        float2 o0 = make_float2(acc[nt][0] + b0, acc[nt][1] + b1);
        float2 o1 = make_float2(acc[nt][2] + b0, acc[nt][3] + b1);
        *(float2*)(C + (size_t)r0 * DM_ + col) = o0;
        *(float2*)(C + (size_t)r1 * DM_ + col) = o1;
    }
}

// ---------------------------------------------------------------------------
// Launch
// ---------------------------------------------------------------------------
extern "C" void kernel_launch(void* const* d_in, const int* in_sizes, int n_in,
                              void* d_out, int out_size) {
    const float* q    = (const float*)d_in[0];
    const float* k    = (const float*)d_in[1];
    const float* v    = (const float*)d_in[2];
    const float* W    = (const float*)d_in[3];
    const float* bias = (const float*)d_in[4];
    float* out = (float*)d_out;

    cudaFuncSetAttribute(attn_mma, cudaFuncAttributeMaxDynamicSharedMemorySize, SM_ATT);
    cudaFuncSetAttribute(proj_mma, cudaFuncAttributeMaxDynamicSharedMemorySize, SM_PROJ);

    attn_mma<<<dim3(S_ / 128, H_, B_), 256, SM_ATT>>>(q, k, v);
    proj_mma<<<dim3(DM_ / 128, (B_ * S_) / 128), 256, SM_PROJ>>>(W, bias, out);
}

// round 7
// speedup vs baseline: 5.0902x; 1.3778x over previous
#include <cuda_runtime.h>
#include <cuda_bf16.h>
#include <stdint.h>

#define B_   2
#define S_   2048
#define H_   16
#define DK_  64
#define DM_  1024
#define QSCALE_ (0.125f * 1.44269504f)   // fold log2(e): softmax via exp2f

#define NTOK (B_ * S_)                   // 4096

// Pre-split bf16 hi/lo operands (written fresh every kernel_launch call)
__device__ __nv_bfloat16 g_qh[(size_t)NTOK * DM_], g_ql[(size_t)NTOK * DM_];
__device__ __nv_bfloat16 g_kh[(size_t)NTOK * DM_], g_kl[(size_t)NTOK * DM_];
__device__ __nv_bfloat16 g_vh[(size_t)NTOK * DM_], g_vl[(size_t)NTOK * DM_];
__device__ __nv_bfloat16 g_wh[(size_t)DM_ * DM_],  g_wl[(size_t)DM_ * DM_];
__device__ __nv_bfloat16 g_ah[(size_t)NTOK * DM_], g_al[(size_t)NTOK * DM_];

// ---------------------------------------------------------------------------
// Helpers (baseline PTX only)
// ---------------------------------------------------------------------------
__device__ __forceinline__ uint32_t smem_u32(const void* p) {
    uint32_t a;
    asm("{ .reg .u64 t; cvta.to.shared.u64 t, %1; cvt.u32.u64 %0, t; }"
        : "=r"(a) : "l"(p));
    return a;
}
#define SW128F(o) ((o) ^ (((o) >> 3) & 0x70))
#define SW64F(o)  ((o) ^ (((o) >> 3) & 0x30))

__device__ __forceinline__ void cpa16(uint32_t dst, const void* src) {
    asm volatile("cp.async.cg.shared.global [%0], [%1], 16;" :: "r"(dst), "l"(src));
}
#define CP_COMMIT() asm volatile("cp.async.commit_group;" ::: "memory")
#define CP_WAIT1()  asm volatile("cp.async.wait_group 1;" ::: "memory")
#define CP_WAIT0()  asm volatile("cp.async.wait_group 0;" ::: "memory")

__device__ __forceinline__ void ldsm4(uint32_t r[4], uint32_t addr) {
    asm volatile("ldmatrix.sync.aligned.m8n8.x4.shared.b16 {%0,%1,%2,%3}, [%4];"
                 : "=r"(r[0]), "=r"(r[1]), "=r"(r[2]), "=r"(r[3]) : "r"(addr));
}
__device__ __forceinline__ void ldsm4t(uint32_t r[4], uint32_t addr) {
    asm volatile("ldmatrix.sync.aligned.m8n8.x4.trans.shared.b16 {%0,%1,%2,%3}, [%4];"
                 : "=r"(r[0]), "=r"(r[1]), "=r"(r[2]), "=r"(r[3]) : "r"(addr));
}
__device__ __forceinline__ void mma16816(float c[4], const uint32_t a[4],
                                         uint32_t b0, uint32_t b1) {
    asm volatile("mma.sync.aligned.m16n8k16.row.col.f32.bf16.bf16.f32 "
                 "{%0,%1,%2,%3}, {%4,%5,%6,%7}, {%8,%9}, {%0,%1,%2,%3};"
                 : "+f"(c[0]), "+f"(c[1]), "+f"(c[2]), "+f"(c[3])
                 : "r"(a[0]), "r"(a[1]), "r"(a[2]), "r"(a[3]), "r"(b0), "r"(b1));
}
__device__ __forceinline__ uint32_t packbf2(float a, float b) {
    __nv_bfloat162 h = __floats2bfloat162_rn(a, b);
    return *(uint32_t*)&h;
}

// ---------------------------------------------------------------------------
// Split: fp32 -> bf16 hi/lo (4 elements per thread)
// ---------------------------------------------------------------------------
__global__ __launch_bounds__(256) void split_k(const float4* __restrict__ src,
                                               uint2* __restrict__ hi,
                                               uint2* __restrict__ lo,
                                               int n4, float scale) {
    int t = blockIdx.x * blockDim.x + threadIdx.x;
    if (t >= n4) return;
    float4 x = src[t];
    x.x *= scale; x.y *= scale; x.z *= scale; x.w *= scale;
    __nv_bfloat16 ha = __float2bfloat16(x.x), hb = __float2bfloat16(x.y);
    __nv_bfloat16 hc = __float2bfloat16(x.z), hd = __float2bfloat16(x.w);
    uint32_t H0, H1;
    { __nv_bfloat162 v = __halves2bfloat162(ha, hb); H0 = *(uint32_t*)&v; }
    { __nv_bfloat162 v = __halves2bfloat162(hc, hd); H1 = *(uint32_t*)&v; }
    hi[t] = make_uint2(H0, H1);
    lo[t] = make_uint2(packbf2(x.x - __bfloat162float(ha), x.y - __bfloat162float(hb)),
                       packbf2(x.z - __bfloat162float(hc), x.w - __bfloat162float(hd)));
}

// ---------------------------------------------------------------------------
// Attention: CTA = (b, h, 128-query tile), 256 threads / 8 warps.
// KV chunks of 64 keys, double-buffered cp.async. Online softmax (log2 domain).
// smem: Qh 16K | Ql 16K | stage0 {Kh,Kl,Vh,Vl}(8K each) | stage1 — 96 KB
// ---------------------------------------------------------------------------
#define AQH 0
#define AQL 16384
#define ASTG 32768
#define ASTG_SZ 32768
#define SM_ATT (ASTG + 2 * ASTG_SZ)   // 98304

__device__ __forceinline__ void attn_issue(uint32_t sb, size_t base, int k0,
                                           int stage, int t) {
    const uint32_t sdst = sb + ASTG + stage * ASTG_SZ;
    const __nv_bfloat16* srcs[4] = {g_kh, g_kl, g_vh, g_vl};
#pragma unroll
    for (int j = 0; j < 8; ++j) {
        int i = t + j * 256;                 // 2048 chunks: 4 tiles x 64 rows x 8
        int tile = i >> 9, r = (i >> 3) & 63, ch = i & 7;
        const __nv_bfloat16* sp = srcs[tile] + base + (size_t)(k0 + r) * DM_ + ch * 8;
        cpa16(sdst + tile * 8192 + SW128F((uint32_t)(r * 128 + ch * 16)), sp);
    }
}

__global__ __launch_bounds__(256, 2) void attn2(void) {
    extern __shared__ char smem[];
    const uint32_t sb = smem_u32(smem);
    const int t = threadIdx.x;
    const int w = t >> 5, l = t & 31;
    const int gid = l >> 2, tid = l & 3;
    const int mq = w * 16;
    const uint32_t lrow = (uint32_t)(l & 15);
    const uint32_t lhalf = (uint32_t)(l & 16);

    const int b = blockIdx.z, h = blockIdx.y, q0 = blockIdx.x * 128;
    const size_t base = (size_t)b * S_ * DM_ + (size_t)h * DK_;

    // Q tiles + stage 0 in one cp.async group
#pragma unroll
    for (int j = 0; j < 8; ++j) {
        int i = t + j * 256;                 // 2048: 2 tiles x 128 rows x 8
        int tile = i >> 10, r = (i >> 3) & 127, ch = i & 7;
        const __nv_bfloat16* sp = (tile ? g_ql : g_qh) + base
                                + (size_t)(q0 + r) * DM_ + ch * 8;
        cpa16(sb + (tile ? AQL : AQH) + SW128F((uint32_t)(r * 128 + ch * 16)), sp);
    }
    attn_issue(sb, base, 0, 0, t);
    CP_COMMIT();

    float accO[8][4];
#pragma unroll
    for (int i = 0; i < 8; ++i)
#pragma unroll
        for (int j = 0; j < 4; ++j) accO[i][j] = 0.0f;
    float m0 = -1e30f, m1 = -1e30f, l0 = 0.0f, l1 = 0.0f;

    for (int c = 0; c < 32; ++c) {
        if (c + 1 < 32) {
            attn_issue(sb, base, (c + 1) * 64, (c + 1) & 1, t);
            CP_COMMIT();
            CP_WAIT1();
        } else {
            CP_WAIT0();
        }
        __syncthreads();
        const uint32_t stg = sb + ASTG + (c & 1) * ASTG_SZ;

        // ---- S = Q K^T (M16 x N64 per warp), 3-pass hi/lo ----
        float accS[8][4];
#pragma unroll
        for (int i = 0; i < 8; ++i)
#pragma unroll
            for (int j = 0; j < 4; ++j) accS[i][j] = 0.0f;

#pragma unroll
        for (int ks = 0; ks < 4; ++ks) {
            uint32_t ah[4], al[4];
            uint32_t swa = SW128F((uint32_t)((mq + lrow) * 128) + ks * 32 + lhalf);
            ldsm4(ah, sb + AQH + swa);
            ldsm4(al, sb + AQL + swa);
#pragma unroll
            for (int np = 0; np < 4; ++np) {
                uint32_t bh[4], bl[4];
                uint32_t swb = SW128F((uint32_t)((np * 16 + lrow) * 128) + ks * 32 + lhalf);
                ldsm4(bh, stg + swb);
                ldsm4(bl, stg + 8192 + swb);
                mma16816(accS[2 * np],     ah, bh[0], bh[2]);
                mma16816(accS[2 * np + 1], ah, bh[1], bh[3]);
                mma16816(accS[2 * np],     ah, bl[0], bl[2]);
                mma16816(accS[2 * np + 1], ah, bl[1], bl[3]);
                mma16816(accS[2 * np],     al, bh[0], bh[2]);
                mma16816(accS[2 * np + 1], al, bh[1], bh[3]);
            }
        }

        // ---- online softmax in log2 domain (scores pre-scaled by log2e) ----
        float mx0 = -1e30f, mx1 = -1e30f;
#pragma unroll
        for (int nt = 0; nt < 8; ++nt) {
            mx0 = fmaxf(mx0, fmaxf(accS[nt][0], accS[nt][1]));
            mx1 = fmaxf(mx1, fmaxf(accS[nt][2], accS[nt][3]));
        }
        mx0 = fmaxf(mx0, __shfl_xor_sync(0xffffffffu, mx0, 1));
        mx0 = fmaxf(mx0, __shfl_xor_sync(0xffffffffu, mx0, 2));
        mx1 = fmaxf(mx1, __shfl_xor_sync(0xffffffffu, mx1, 1));
        mx1 = fmaxf(mx1, __shfl_xor_sync(0xffffffffu, mx1, 2));
        float mn0 = fmaxf(m0, mx0), mn1 = fmaxf(m1, mx1);
        float c0 = exp2f(m0 - mn0), c1 = exp2f(m1 - mn1);
        m0 = mn0; m1 = mn1;

        float s0 = 0.0f, s1 = 0.0f;
#pragma unroll
        for (int nt = 0; nt < 8; ++nt) {
            float p0 = exp2f(accS[nt][0] - mn0);
            float p1 = exp2f(accS[nt][1] - mn0);
            float p2 = exp2f(accS[nt][2] - mn1);
            float p3 = exp2f(accS[nt][3] - mn1);
            s0 += p0 + p1; s1 += p2 + p3;
            accS[nt][0] = p0; accS[nt][1] = p1; accS[nt][2] = p2; accS[nt][3] = p3;
        }
        s0 += __shfl_xor_sync(0xffffffffu, s0, 1);
        s0 += __shfl_xor_sync(0xffffffffu, s0, 2);
        s1 += __shfl_xor_sync(0xffffffffu, s1, 1);
        s1 += __shfl_xor_sync(0xffffffffu, s1, 2);
        l0 = l0 * c0 + s0;
        l1 = l1 * c1 + s1;
#pragma unroll
        for (int nt = 0; nt < 8; ++nt) {
            accO[nt][0] *= c0; accO[nt][1] *= c0;
            accO[nt][2] *= c1; accO[nt][3] *= c1;
        }

        // ---- O += P V (P in registers; V via ldmatrix.trans) ----
#pragma unroll
        for (int kk = 0; kk < 4; ++kk) {
            uint32_t ph[4], pl[4];
#pragma unroll
            for (int half = 0; half < 2; ++half) {
                float pA = accS[2 * kk + half][0], pB = accS[2 * kk + half][1];
                float pC = accS[2 * kk + half][2], pD = accS[2 * kk + half][3];
                __nv_bfloat16 hA = __float2bfloat16(pA), hB = __float2bfloat16(pB);
                __nv_bfloat16 hC = __float2bfloat16(pC), hD = __float2bfloat16(pD);
                { __nv_bfloat162 vv = __halves2bfloat162(hA, hB); ph[2 * half] = *(uint32_t*)&vv; }
                { __nv_bfloat162 vv = __halves2bfloat162(hC, hD); ph[2 * half + 1] = *(uint32_t*)&vv; }
                pl[2 * half]     = packbf2(pA - __bfloat162float(hA), pB - __bfloat162float(hB));
                pl[2 * half + 1] = packbf2(pC - __bfloat162float(hC), pD - __bfloat162float(hD));
            }
#pragma unroll
            for (int np = 0; np < 4; ++np) {
                uint32_t vh[4], vl[4];
                uint32_t swv = SW128F((uint32_t)((kk * 16 + lrow) * 128) + np * 32 + lhalf);
                ldsm4t(vh, stg + 16384 + swv);
                ldsm4t(vl, stg + 24576 + swv);
                mma16816(accO[2 * np],     ph, vh[0], vh[1]);
                mma16816(accO[2 * np + 1], ph, vh[2], vh[3]);
                mma16816(accO[2 * np],     ph, vl[0], vl[1]);
                mma16816(accO[2 * np + 1], ph, vl[2], vl[3]);
                mma16816(accO[2 * np],     pl, vh[0], vh[1]);
                mma16816(accO[2 * np + 1], pl, vh[2], vh[3]);
            }
        }
        __syncthreads();
    }

    // ---- epilogue: normalize + write hi/lo bf16 (proj input format) ----
    float inv0 = 1.0f / l0, inv1 = 1.0f / l1;
    const int r0 = q0 + mq + gid, r1 = r0 + 8;
#pragma unroll
    for (int nt = 0; nt < 8; ++nt) {
        int col = nt * 8 + 2 * tid;
        float v0 = accO[nt][0] * inv0, v1 = accO[nt][1] * inv0;
        float v2 = accO[nt][2] * inv1, v3 = accO[nt][3] * inv1;
        __nv_bfloat16 h0 = __float2bfloat16(v0), h1 = __float2bfloat16(v1);
        __nv_bfloat16 h2 = __float2bfloat16(v2), h3 = __float2bfloat16(v3);
        uint32_t H0, H2;
        { __nv_bfloat162 vv = __halves2bfloat162(h0, h1); H0 = *(uint32_t*)&vv; }
        { __nv_bfloat162 vv = __halves2bfloat162(h2, h3); H2 = *(uint32_t*)&vv; }
        *(uint32_t*)(g_ah + base + (size_t)r0 * DM_ + col) = H0;
        *(uint32_t*)(g_al + base + (size_t)r0 * DM_ + col) =
            packbf2(v0 - __bfloat162float(h0), v1 - __bfloat162float(h1));
        *(uint32_t*)(g_ah + base + (size_t)r1 * DM_ + col) = H2;
        *(uint32_t*)(g_al + base + (size_t)r1 * DM_ + col) =
            packbf2(v2 - __bfloat162float(h2), v3 - __bfloat162float(h3));
    }
}

// ---------------------------------------------------------------------------
// Projection: C[4096,1024] = A @ W^T + bias. 128x128 tile/CTA, K-chunks of 32,
// SW64 swizzle (64B rows), double-buffered cp.async. 2 CTAs/SM, single wave.
// smem: 2 stages x {Ah,Al,Wh,Wl}(8K each) = 64 KB
// ---------------------------------------------------------------------------
#define PSTG_SZ 32768
#define SM_PROJ (2 * PSTG_SZ)

__device__ __forceinline__ void proj_issue(uint32_t sb, int i0, int j0, int kc,
                                           int stage, int t) {
    const uint32_t sdst = sb + stage * PSTG_SZ;
    const __nv_bfloat16* srcs[4] = {g_ah + (size_t)i0 * DM_, g_al + (size_t)i0 * DM_,
                                    g_wh + (size_t)j0 * DM_, g_wl + (size_t)j0 * DM_};
#pragma unroll
    for (int j = 0; j < 8; ++j) {
        int i = t + j * 256;                 // 2048: 4 tiles x 128 rows x 4
        int tile = i >> 9, r = (i >> 2) & 127, ch = i & 3;
        const __nv_bfloat16* sp = srcs[tile] + (size_t)r * DM_ + kc * 32 + ch * 8;
        cpa16(sdst + tile * 8192 + SW64F((uint32_t)(r * 64 + ch * 16)), sp);
    }
}

__global__ __launch_bounds__(256, 2) void proj2(const float* __restrict__ bias,
                                                float* __restrict__ C) {
    extern __shared__ char smem[];
    const uint32_t sb = smem_u32(smem);
    const int t = threadIdx.x;
    const int w = t >> 5, l = t & 31;
    const int gid = l >> 2, tid = l & 3;
    const int mq = w * 16;
    const uint32_t lrow = (uint32_t)(l & 15);
    const uint32_t lhalf = (uint32_t)(l & 16);
    const int j0 = blockIdx.x * 128, i0 = blockIdx.y * 128;

    float acc[16][4];
#pragma unroll
    for (int i = 0; i < 16; ++i)
#pragma unroll
        for (int j = 0; j < 4; ++j) acc[i][j] = 0.0f;

    proj_issue(sb, i0, j0, 0, 0, t);
    CP_COMMIT();

    for (int kc = 0; kc < 32; ++kc) {
        if (kc + 1 < 32) {
            proj_issue(sb, i0, j0, kc + 1, (kc + 1) & 1, t);
            CP_COMMIT();
            CP_WAIT1();
        } else {
            CP_WAIT0();
        }
        __syncthreads();
        const uint32_t stg = sb + (kc & 1) * PSTG_SZ;

#pragma unroll
        for (int ks = 0; ks < 2; ++ks) {
            uint32_t ah[4], al[4];
            uint32_t swa = SW64F((uint32_t)((mq + lrow) * 64) + ks * 32 + lhalf);
            ldsm4(ah, stg + swa);
            ldsm4(al, stg + 8192 + swa);
#pragma unroll
            for (int np = 0; np < 8; ++np) {
                uint32_t bh[4], bl[4];
                uint32_t swb = SW64F((uint32_t)((np * 16 + lrow) * 64) + ks * 32 + lhalf);
                ldsm4(bh, stg + 16384 + swb);
                ldsm4(bl, stg + 24576 + swb);
                mma16816(acc[2 * np],     ah, bh[0], bh[2]);
                mma16816(acc[2 * np + 1], ah, bh[1], bh[3]);
                mma16816(acc[2 * np],     ah, bl[0], bl[2]);
                mma16816(acc[2 * np + 1], ah, bl[1], bl[3]);
                mma16816(acc[2 * np],     al, bh[0], bh[2]);
                mma16816(acc[2 * np + 1], al, bh[1], bh[3]);
            }
        }
        __syncthreads();
    }

    const int r0 = i0 + mq + gid, r1 = r0 + 8;
#pragma unroll
    for (int nt = 0; nt < 16; ++nt) {
        int col = j0 + nt * 8 + 2 * tid;
        float b0 = bias[col], b1 = bias[col + 1];
        float2 o0 = make_float2(acc[nt][0] + b0, acc[nt][1] + b1);
        float2 o1 = make_float2(acc[nt][2] + b0, acc[nt][3] + b1);
        *(float2*)(C + (size_t)r0 * DM_ + col) = o0;
        *(float2*)(C + (size_t)r1 * DM_ + col) = o1;
    }
}

// ---------------------------------------------------------------------------
// Launch
// ---------------------------------------------------------------------------
extern "C" void kernel_launch(void* const* d_in, const int* in_sizes, int n_in,
                              void* d_out, int out_size) {
    const float* q    = (const float*)d_in[0];
    const float* k    = (const float*)d_in[1];
    const float* v    = (const float*)d_in[2];
    const float* W    = (const float*)d_in[3];
    const float* bias = (const float*)d_in[4];
    float* out = (float*)d_out;

    __nv_bfloat16 *qh, *ql, *kh, *kl, *vh, *vl, *wh, *wl;
    cudaGetSymbolAddress((void**)&qh, g_qh); cudaGetSymbolAddress((void**)&ql, g_ql);
    cudaGetSymbolAddress((void**)&kh, g_kh); cudaGetSymbolAddress((void**)&kl, g_kl);
    cudaGetSymbolAddress((void**)&vh, g_vh); cudaGetSymbolAddress((void**)&vl, g_vl);
    cudaGetSymbolAddress((void**)&wh, g_wh); cudaGetSymbolAddress((void**)&wl, g_wl);

    cudaFuncSetAttribute(attn2, cudaFuncAttributeMaxDynamicSharedMemorySize, SM_ATT);
    cudaFuncSetAttribute(proj2, cudaFuncAttributeMaxDynamicSharedMemorySize, SM_PROJ);

    const int n4_qkv = NTOK * DM_ / 4;   // 1,048,576
    const int n4_w   = DM_ * DM_ / 4;    //   262,144
    split_k<<<n4_qkv / 256, 256>>>((const float4*)q, (uint2*)qh, (uint2*)ql, n4_qkv, QSCALE_);
    split_k<<<n4_qkv / 256, 256>>>((const float4*)k, (uint2*)kh, (uint2*)kl, n4_qkv, 1.0f);
    split_k<<<n4_qkv / 256, 256>>>((const float4*)v, (uint2*)vh, (uint2*)vl, n4_qkv, 1.0f);
    split_k<<<n4_w / 256, 256>>>((const float4*)W, (uint2*)wh, (uint2*)wl, n4_w, 1.0f);

    attn2<<<dim3(S_ / 128, H_, B_), 256, SM_ATT>>>();
    proj2<<<dim3(DM_ / 128, NTOK / 128), 256, SM_PROJ>>>(bias, out);
}

// round 8
// speedup vs baseline: 5.4044x; 1.0617x over previous
#include <cuda_runtime.h>
#include <cuda_bf16.h>
#include <stdint.h>

#define B_   2
#define S_   2048
#define H_   16
#define DK_  64
#define DM_  1024
#define QSCALE_ (0.125f * 1.44269504f)   // fold log2(e): softmax via exp2f

#define NTOK (B_ * S_)                   // 4096

// Pre-split bf16 hi/lo operands (written fresh every kernel_launch call)
__device__ __nv_bfloat16 g_qh[(size_t)NTOK * DM_], g_ql[(size_t)NTOK * DM_];
__device__ __nv_bfloat16 g_kh[(size_t)NTOK * DM_], g_kl[(size_t)NTOK * DM_];
__device__ __nv_bfloat16 g_vh[(size_t)NTOK * DM_], g_vl[(size_t)NTOK * DM_];
__device__ __nv_bfloat16 g_wh[(size_t)DM_ * DM_],  g_wl[(size_t)DM_ * DM_];
__device__ __nv_bfloat16 g_ah[(size_t)NTOK * DM_], g_al[(size_t)NTOK * DM_];

// ---------------------------------------------------------------------------
// Helpers (baseline PTX only)
// ---------------------------------------------------------------------------
__device__ __forceinline__ uint32_t smem_u32(const void* p) {
    uint32_t a;
    asm("{ .reg .u64 t; cvta.to.shared.u64 t, %1; cvt.u32.u64 %0, t; }"
        : "=r"(a) : "l"(p));
    return a;
}
#define SW128F(o) ((o) ^ (((o) >> 3) & 0x70))
#define SW64F(o)  ((o) ^ (((o) >> 3) & 0x30))

__device__ __forceinline__ void cpa16(uint32_t dst, const void* src) {
    asm volatile("cp.async.cg.shared.global [%0], [%1], 16;" :: "r"(dst), "l"(src));
}
#define CP_COMMIT() asm volatile("cp.async.commit_group;" ::: "memory")
#define CP_WAIT1()  asm volatile("cp.async.wait_group 1;" ::: "memory")
#define CP_WAIT0()  asm volatile("cp.async.wait_group 0;" ::: "memory")

__device__ __forceinline__ void ldsm4(uint32_t r[4], uint32_t addr) {
    asm volatile("ldmatrix.sync.aligned.m8n8.x4.shared.b16 {%0,%1,%2,%3}, [%4];"
                 : "=r"(r[0]), "=r"(r[1]), "=r"(r[2]), "=r"(r[3]) : "r"(addr));
}
__device__ __forceinline__ void ldsm4t(uint32_t r[4], uint32_t addr) {
    asm volatile("ldmatrix.sync.aligned.m8n8.x4.trans.shared.b16 {%0,%1,%2,%3}, [%4];"
                 : "=r"(r[0]), "=r"(r[1]), "=r"(r[2]), "=r"(r[3]) : "r"(addr));
}
__device__ __forceinline__ void mma16816(float c[4], const uint32_t a[4],
                                         uint32_t b0, uint32_t b1) {
    asm volatile("mma.sync.aligned.m16n8k16.row.col.f32.bf16.bf16.f32 "
                 "{%0,%1,%2,%3}, {%4,%5,%6,%7}, {%8,%9}, {%0,%1,%2,%3};"
                 : "+f"(c[0]), "+f"(c[1]), "+f"(c[2]), "+f"(c[3])
                 : "r"(a[0]), "r"(a[1]), "r"(a[2]), "r"(a[3]), "r"(b0), "r"(b1));
}
__device__ __forceinline__ uint32_t packbf2(float a, float b) {
    __nv_bfloat162 h = __floats2bfloat162_rn(a, b);
    return *(uint32_t*)&h;
}
// Fast hi/lo split of a float pair: hi = truncation (exact, 1 PRMT),
// lo = rn(x - hi) (captures the remainder; combined error ~2^-16)
__device__ __forceinline__ void split2(float a, float b, uint32_t& hi, uint32_t& lo) {
    uint32_t A = __float_as_uint(a), Bb = __float_as_uint(b);
    hi = __byte_perm(A, Bb, 0x7632);
    float la = a - __uint_as_float(A & 0xffff0000u);
    float lb = b - __uint_as_float(Bb & 0xffff0000u);
    lo = packbf2(la, lb);
}

// ---------------------------------------------------------------------------
// Fused split: q,k,v,W -> bf16 hi/lo in one launch
// ---------------------------------------------------------------------------
#define N4QKV (NTOK * DM_ / 4)   // 1048576
#define N4W   (DM_ * DM_ / 4)    //  262144
#define N4TOT (3 * N4QKV + N4W)  // 3407872

__global__ __launch_bounds__(256) void split_all(const float4* __restrict__ q,
                                                 const float4* __restrict__ k,
                                                 const float4* __restrict__ v,
                                                 const float4* __restrict__ W) {
    int t = blockIdx.x * 256 + threadIdx.x;
    if (t >= N4TOT) return;
    const float4* src;
    uint2 *hi, *lo;
    float scale = 1.0f;
    int idx;
    if (t < N4QKV) {
        src = q; hi = (uint2*)g_qh; lo = (uint2*)g_ql; idx = t; scale = QSCALE_;
    } else if (t < 2 * N4QKV) {
        src = k; hi = (uint2*)g_kh; lo = (uint2*)g_kl; idx = t - N4QKV;
    } else if (t < 3 * N4QKV) {
        src = v; hi = (uint2*)g_vh; lo = (uint2*)g_vl; idx = t - 2 * N4QKV;
    } else {
        src = W; hi = (uint2*)g_wh; lo = (uint2*)g_wl; idx = t - 3 * N4QKV;
    }
    float4 x = src[idx];
    x.x *= scale; x.y *= scale; x.z *= scale; x.w *= scale;
    uint32_t h0, l0, h1, l1;
    split2(x.x, x.y, h0, l0);
    split2(x.z, x.w, h1, l1);
    hi[idx] = make_uint2(h0, h1);
    lo[idx] = make_uint2(l0, l1);
}

// ---------------------------------------------------------------------------
// Attention: CTA = (b, h, 128-query tile), 256 threads / 8 warps.
// KV chunks of 64 keys, 2-stage cp.async ring, ONE __syncthreads per chunk
// (wait -> sync -> issue next -> compute). Online softmax in log2 domain.
// smem: Qh 16K | Ql 16K | stage0 {Kh,Kl,Vh,Vl}(8K each) | stage1 — 96 KB
// ---------------------------------------------------------------------------
#define AQH 0
#define AQL 16384
#define ASTG 32768
#define ASTG_SZ 32768
#define SM_ATT (ASTG + 2 * ASTG_SZ)   // 98304

__device__ __forceinline__ void attn_issue(uint32_t sb, size_t base, int k0,
                                           int stage, int t) {
    const uint32_t sdst = sb + ASTG + stage * ASTG_SZ;
    const __nv_bfloat16* srcs[4] = {g_kh, g_kl, g_vh, g_vl};
#pragma unroll
    for (int j = 0; j < 8; ++j) {
        int i = t + j * 256;                 // 2048 chunks: 4 tiles x 64 rows x 8
        int tile = i >> 9, r = (i >> 3) & 63, ch = i & 7;
        const __nv_bfloat16* sp = srcs[tile] + base + (size_t)(k0 + r) * DM_ + ch * 8;
        cpa16(sdst + tile * 8192 + SW128F((uint32_t)(r * 128 + ch * 16)), sp);
    }
}

__global__ __launch_bounds__(256, 2) void attn2(void) {
    extern __shared__ char smem[];
    const uint32_t sb = smem_u32(smem);
    const int t = threadIdx.x;
    const int w = t >> 5, l = t & 31;
    const int gid = l >> 2, tid = l & 3;
    const int mq = w * 16;
    const uint32_t lrow = (uint32_t)(l & 15);
    const uint32_t lhalf = (uint32_t)(l & 16);

    const int b = blockIdx.z, h = blockIdx.y, q0 = blockIdx.x * 128;
    const size_t base = (size_t)b * S_ * DM_ + (size_t)h * DK_;

    // Q tiles + stage 0 in one cp.async group
#pragma unroll
    for (int j = 0; j < 8; ++j) {
        int i = t + j * 256;                 // 2048: 2 tiles x 128 rows x 8
        int tile = i >> 10, r = (i >> 3) & 127, ch = i & 7;
        const __nv_bfloat16* sp = (tile ? g_ql : g_qh) + base
                                + (size_t)(q0 + r) * DM_ + ch * 8;
        cpa16(sb + (tile ? AQL : AQH) + SW128F((uint32_t)(r * 128 + ch * 16)), sp);
    }
    attn_issue(sb, base, 0, 0, t);
    CP_COMMIT();

    float accO[8][4];
#pragma unroll
    for (int i = 0; i < 8; ++i)
#pragma unroll
        for (int j = 0; j < 4; ++j) accO[i][j] = 0.0f;
    float m0 = -1e30f, m1 = -1e30f, l0 = 0.0f, l1 = 0.0f;

    for (int c = 0; c < 32; ++c) {
        CP_WAIT0();          // chunk c resident (exactly one group in flight)
        __syncthreads();     // all warps past previous compute -> recycled stage free
        if (c + 1 < 32) attn_issue(sb, base, (c + 1) * 64, (c + 1) & 1, t);
        CP_COMMIT();
        const uint32_t stg = sb + ASTG + (c & 1) * ASTG_SZ;

        // ---- S = Q K^T (M16 x N64 per warp), 3-pass hi/lo ----
        float accS[8][4];
#pragma unroll
        for (int i = 0; i < 8; ++i)
#pragma unroll
            for (int j = 0; j < 4; ++j) accS[i][j] = 0.0f;

#pragma unroll
        for (int ks = 0; ks < 4; ++ks) {
            uint32_t ah[4], al[4];
            uint32_t swa = SW128F((uint32_t)((mq + lrow) * 128) + ks * 32 + lhalf);
            ldsm4(ah, sb + AQH + swa);
            ldsm4(al, sb + AQL + swa);
#pragma unroll
            for (int np = 0; np < 4; ++np) {
                uint32_t bh[4], bl[4];
                uint32_t swb = SW128F((uint32_t)((np * 16 + lrow) * 128) + ks * 32 + lhalf);
                ldsm4(bh, stg + swb);
                ldsm4(bl, stg + 8192 + swb);
                mma16816(accS[2 * np],     ah, bh[0], bh[2]);
                mma16816(accS[2 * np + 1], ah, bh[1], bh[3]);
                mma16816(accS[2 * np],     ah, bl[0], bl[2]);
                mma16816(accS[2 * np + 1], ah, bl[1], bl[3]);
                mma16816(accS[2 * np],     al, bh[0], bh[2]);
                mma16816(accS[2 * np + 1], al, bh[1], bh[3]);
            }
        }

        // ---- online softmax in log2 domain (scores pre-scaled by log2e) ----
        float mx0 = -1e30f, mx1 = -1e30f;
#pragma unroll
        for (int nt = 0; nt < 8; ++nt) {
            mx0 = fmaxf(mx0, fmaxf(accS[nt][0], accS[nt][1]));
            mx1 = fmaxf(mx1, fmaxf(accS[nt][2], accS[nt][3]));
        }
        mx0 = fmaxf(mx0, __shfl_xor_sync(0xffffffffu, mx0, 1));
        mx0 = fmaxf(mx0, __shfl_xor_sync(0xffffffffu, mx0, 2));
        mx1 = fmaxf(mx1, __shfl_xor_sync(0xffffffffu, mx1, 1));
        mx1 = fmaxf(mx1, __shfl_xor_sync(0xffffffffu, mx1, 2));
        float mn0 = fmaxf(m0, mx0), mn1 = fmaxf(m1, mx1);
        float c0 = exp2f(m0 - mn0), c1 = exp2f(m1 - mn1);
        m0 = mn0; m1 = mn1;

        float s0 = 0.0f, s1 = 0.0f;
#pragma unroll
        for (int nt = 0; nt < 8; ++nt) {
            float p0 = exp2f(accS[nt][0] - mn0);
            float p1 = exp2f(accS[nt][1] - mn0);
            float p2 = exp2f(accS[nt][2] - mn1);
            float p3 = exp2f(accS[nt][3] - mn1);
            s0 += p0 + p1; s1 += p2 + p3;
            accS[nt][0] = p0; accS[nt][1] = p1; accS[nt][2] = p2; accS[nt][3] = p3;
        }
        s0 += __shfl_xor_sync(0xffffffffu, s0, 1);
        s0 += __shfl_xor_sync(0xffffffffu, s0, 2);
        s1 += __shfl_xor_sync(0xffffffffu, s1, 1);
        s1 += __shfl_xor_sync(0xffffffffu, s1, 2);
        l0 = l0 * c0 + s0;
        l1 = l1 * c1 + s1;
#pragma unroll
        for (int nt = 0; nt < 8; ++nt) {
            accO[nt][0] *= c0; accO[nt][1] *= c0;
            accO[nt][2] *= c1; accO[nt][3] *= c1;
        }

        // ---- O += P V (P in registers via PRMT split; V via ldmatrix.trans) ----
#pragma unroll
        for (int kk = 0; kk < 4; ++kk) {
            uint32_t ph[4], pl[4];
#pragma unroll
            for (int half = 0; half < 2; ++half) {
                split2(accS[2 * kk + half][0], accS[2 * kk + half][1],
                       ph[2 * half], pl[2 * half]);
                split2(accS[2 * kk + half][2], accS[2 * kk + half][3],
                       ph[2 * half + 1], pl[2 * half + 1]);
            }
#pragma unroll
            for (int np = 0; np < 4; ++np) {
                uint32_t vh[4], vl[4];
                uint32_t swv = SW128F((uint32_t)((kk * 16 + lrow) * 128) + np * 32 + lhalf);
                ldsm4t(vh, stg + 16384 + swv);
                ldsm4t(vl, stg + 24576 + swv);
                mma16816(accO[2 * np],     ph, vh[0], vh[1]);
                mma16816(accO[2 * np + 1], ph, vh[2], vh[3]);
                mma16816(accO[2 * np],     ph, vl[0], vl[1]);
                mma16816(accO[2 * np + 1], ph, vl[2], vl[3]);
                mma16816(accO[2 * np],     pl, vh[0], vh[1]);
                mma16816(accO[2 * np + 1], pl, vh[2], vh[3]);
            }
        }
    }

    // ---- epilogue: normalize + write hi/lo bf16 (proj input format) ----
    float inv0 = 1.0f / l0, inv1 = 1.0f / l1;
    const int r0 = q0 + mq + gid, r1 = r0 + 8;
#pragma unroll
    for (int nt = 0; nt < 8; ++nt) {
        int col = nt * 8 + 2 * tid;
        uint32_t H0, L0, H2, L2;
        split2(accO[nt][0] * inv0, accO[nt][1] * inv0, H0, L0);
        split2(accO[nt][2] * inv1, accO[nt][3] * inv1, H2, L2);
        *(uint32_t*)(g_ah + base + (size_t)r0 * DM_ + col) = H0;
        *(uint32_t*)(g_al + base + (size_t)r0 * DM_ + col) = L0;
        *(uint32_t*)(g_ah + base + (size_t)r1 * DM_ + col) = H2;
        *(uint32_t*)(g_al + base + (size_t)r1 * DM_ + col) = L2;
    }
}

// ---------------------------------------------------------------------------
// Projection: C[4096,1024] = A @ W^T + bias. 128x128 tile/CTA, K-chunks of 32,
// SW64 swizzle, 3-stage cp.async ring, ONE __syncthreads per chunk.
// smem: 3 stages x {Ah,Al,Wh,Wl}(8K each) = 96 KB; 2 CTAs/SM, single wave.
// ---------------------------------------------------------------------------
#define PSTG_SZ 32768
#define SM_PROJ (3 * PSTG_SZ)   // 98304

__device__ __forceinline__ void proj_issue(uint32_t sb, int i0, int j0, int kc,
                                           int stage, int t) {
    const uint32_t sdst = sb + stage * PSTG_SZ;
    const __nv_bfloat16* srcs[4] = {g_ah + (size_t)i0 * DM_, g_al + (size_t)i0 * DM_,
                                    g_wh + (size_t)j0 * DM_, g_wl + (size_t)j0 * DM_};
#pragma unroll
    for (int j = 0; j < 8; ++j) {
        int i = t + j * 256;                 // 2048: 4 tiles x 128 rows x 4
        int tile = i >> 9, r = (i >> 2) & 127, ch = i & 3;
        const __nv_bfloat16* sp = srcs[tile] + (size_t)r * DM_ + kc * 32 + ch * 8;
        cpa16(sdst + tile * 8192 + SW64F((uint32_t)(r * 64 + ch * 16)), sp);
    }
}

__global__ __launch_bounds__(256, 2) void proj2(const float* __restrict__ bias,
                                                float* __restrict__ C) {
    extern __shared__ char smem[];
    const uint32_t sb = smem_u32(smem);
    const int t = threadIdx.x;
    const int w = t >> 5, l = t & 31;
    const int gid = l >> 2, tid = l & 3;
    const int mq = w * 16;
    const uint32_t lrow = (uint32_t)(l & 15);
    const uint32_t lhalf = (uint32_t)(l & 16);
    const int j0 = blockIdx.x * 128, i0 = blockIdx.y * 128;

    float acc[16][4];
#pragma unroll
    for (int i = 0; i < 16; ++i)
#pragma unroll
        for (int j = 0; j < 4; ++j) acc[i][j] = 0.0f;

    proj_issue(sb, i0, j0, 0, 0, t);
    CP_COMMIT();
    proj_issue(sb, i0, j0, 1, 1, t);
    CP_COMMIT();

    int s2 = 2;   // stage of chunk kc+2 (mod-3 counter, no divide)
    for (int kc = 0; kc < 32; ++kc) {
        CP_WAIT1();          // chunk kc resident (pending <= {kc+1})
        __syncthreads();     // all warps past compute(kc-1) -> stage s2 free
        if (kc + 2 < 32) proj_issue(sb, i0, j0, kc + 2, s2, t);
        CP_COMMIT();         // unconditional: keeps group counting valid at tail
        const int scur = (s2 + 1 >= 3) ? s2 + 1 - 3 : s2 + 1;   // == kc % 3
        const uint32_t stg = sb + scur * PSTG_SZ;
        if (++s2 >= 3) s2 = 0;

#pragma unroll
        for (int ks = 0; ks < 2; ++ks) {
            uint32_t ah[4], al[4];
            uint32_t swa = SW64F((uint32_t)((mq + lrow) * 64) + ks * 32 + lhalf);
            ldsm4(ah, stg + swa);
            ldsm4(al, stg + 8192 + swa);
#pragma unroll
            for (int np = 0; np < 8; ++np) {
                uint32_t bh[4], bl[4];
                uint32_t swb = SW64F((uint32_t)((np * 16 + lrow) * 64) + ks * 32 + lhalf);
                ldsm4(bh, stg + 16384 + swb);
                ldsm4(bl, stg + 24576 + swb);
                mma16816(acc[2 * np],     ah, bh[0], bh[2]);
                mma16816(acc[2 * np + 1], ah, bh[1], bh[3]);
                mma16816(acc[2 * np],     ah, bl[0], bl[2]);
                mma16816(acc[2 * np + 1], ah, bl[1], bl[3]);
                mma16816(acc[2 * np],     al, bh[0], bh[2]);
                mma16816(acc[2 * np + 1], al, bh[1], bh[3]);
            }
        }
    }

    const int r0 = i0 + mq + gid, r1 = r0 + 8;
#pragma unroll
    for (int nt = 0; nt < 16; ++nt) {
        int col = j0 + nt * 8 + 2 * tid;
        float b0 = bias[col], b1 = bias[col + 1];
        float2 o0 = make_float2(acc[nt][0] + b0, acc[nt][1] + b1);
        float2 o1 = make_float2(acc[nt][2] + b0, acc[nt][3] + b1);
        *(float2*)(C + (size_t)r0 * DM_ + col) = o0;
        *(float2*)(C + (size_t)r1 * DM_ + col) = o1;
    }
}

// ---------------------------------------------------------------------------
// Launch
// ---------------------------------------------------------------------------
extern "C" void kernel_launch(void* const* d_in, const int* in_sizes, int n_in,
                              void* d_out, int out_size) {
    const float* q    = (const float*)d_in[0];
    const float* k    = (const float*)d_in[1];
    const float* v    = (const float*)d_in[2];
    const float* W    = (const float*)d_in[3];
    const float* bias = (const float*)d_in[4];
    float* out = (float*)d_out;

    cudaFuncSetAttribute(attn2, cudaFuncAttributeMaxDynamicSharedMemorySize, SM_ATT);
    cudaFuncSetAttribute(proj2, cudaFuncAttributeMaxDynamicSharedMemorySize, SM_PROJ);

    split_all<<<(N4TOT + 255) / 256, 256>>>((const float4*)q, (const float4*)k,
                                            (const float4*)v, (const float4*)W);
    attn2<<<dim3(S_ / 128, H_, B_), 256, SM_ATT>>>();
    proj2<<<dim3(DM_ / 128, NTOK / 128), 256, SM_PROJ>>>(bias, out);
}